// round 10
// baseline (speedup 1.0000x reference)
#include <cuda_runtime.h>
#include <cstdint>

// Problem constants (fixed shapes per reference)
#define B_DIM 4
#define P_DIM 2
#define T_DIM 1024
#define F_DIM 1024
#define D_DIM 16
#define CHUNK 128
#define NCHUNK (F_DIM / CHUNK)   // 8
#define T_PER_BLOCK 8

// Per-(b,d,chunk) integer shifts. 4*16*8 = 512 ints.
__device__ int g_shift[B_DIM * D_DIM * NCHUNK];

// ---------------------------------------------------------------------------
// Kernel 1 (tiny): compute the 512 chunk shifts. One block, 512 threads,
// thread (bd, c) does the sequential rounded-product sum that exactly
// reproduces the reference's trunc(chunk_mean) (rel_err == 0.0 verified).
// Publishes g_shift, then triggers PDL dependents.
// ---------------------------------------------------------------------------
__global__ void dedisp_prep_kernel(const float* __restrict__ dm,
                                   const float* __restrict__ df)
{
    const int idx = threadIdx.x;          // 0..511
    const int bd  = idx >> 3;             // (b*16 + d)
    const int c   = idx & (NCHUNK - 1);   // chunk

    const float dmv = dm[bd];
    const float* base = df + c * CHUNK;

    float sum = 0.0f;
    #pragma unroll 16
    for (int i = 0; i < CHUNK; i++)
        sum = __fadd_rn(sum, __fmul_rn(dmv, base[i]));  // round mul, then add

    const float mean = __fmul_rn(sum, 0.0078125f);       // exact *2^-7
    int s = (int)truncf(mean);
    if (s < 0) s = 0;
    g_shift[idx] = s & (T_DIM - 1);

    __threadfence();
    // Allow the PDL-dependent gather grid to launch now.
    asm volatile("griddepcontrol.launch_dependents;" ::: "memory");
}

// ---------------------------------------------------------------------------
// Kernel 2: the gather-copy (identical memory behavior to the 83.2us R7
// kernel: float4 loads via __ldg, normal float4 stores).
// grid = B*D*P*(T/T_PER_BLOCK) = 16384 blocks, 256 threads.
// Warp w handles chunk w -> shift is warp-uniform.
// The delays tail is written by the 64 (p==0, tb==0) blocks BEFORE the
// grid-dependency wait, so it overlaps the prep kernel.
// ---------------------------------------------------------------------------
__global__ __launch_bounds__(256)
void dedisp_gather_kernel(const float4* __restrict__ x,
                          float4*       __restrict__ out,
                          const float*  __restrict__ dm,
                          const float*  __restrict__ df,
                          float*        __restrict__ delays)
{
    const int bi = blockIdx.x;
    const int tb = bi & (T_DIM / T_PER_BLOCK - 1);   // 0..127
    const int p  = (bi >> 7) & (P_DIM - 1);
    const int d  = (bi >> 8) & (D_DIM - 1);
    const int b  = bi >> 12;
    const int bd = b * D_DIM + d;

    const int tid = threadIdx.x;          // 0..255, f4 index
    const int c   = tid >> 5;             // chunk = warp id

    // Pre-wait work: delays tail (independent of shifts).
    if (p == 0 && tb == 0) {
        const float dmv = dm[bd];
        float* drow = delays + (size_t)bd * F_DIM;
        #pragma unroll
        for (int j = 0; j < 4; j++) {
            const int f = tid + j * 256;                 // coalesced
            drow[f] = __fmul_rn(dmv, df[f]);
        }
    }

    // Wait for the prep kernel's g_shift to be published (PDL).
    asm volatile("griddepcontrol.wait;" ::: "memory");

    const int s = g_shift[bd * NCHUNK + c];

    const int F4 = F_DIM / 4;             // 256 float4 per row

    const float4* __restrict__ xrow =
        x + (size_t)(b * P_DIM + p) * T_DIM * F4;

    float4* __restrict__ orow =
        out + ((size_t)(bd * P_DIM + p) * T_DIM
               + (size_t)tb * T_PER_BLOCK) * F4 + tid;

    const int t0 = tb * T_PER_BLOCK;

    #pragma unroll
    for (int k = 0; k < T_PER_BLOCK; k++) {
        int ts = t0 + k + s;
        if (ts >= T_DIM) ts -= T_DIM;     // s < 1024, t < 1024 -> one subtract
        orow[k * F4] = __ldg(&xrow[(size_t)ts * F4 + tid]);
    }
}

// ---------------------------------------------------------------------------
// Launch: prep, then gather as a PDL-dependent launch on the same stream.
// ---------------------------------------------------------------------------
extern "C" void kernel_launch(void* const* d_in, const int* in_sizes, int n_in,
                              void* d_out, int out_size)
{
    const float* x  = (const float*)d_in[0];   // (4,2,1024,1024)
    const float* dm = (const float*)d_in[1];   // (4,16)
    const float* df = (const float*)d_in[2];   // (1024,)

    float* out = (float*)d_out;
    // Output layout: dedispersed (4,16,2,1024,1024) then delays (4,16,1024)
    float* delays = out + (size_t)B_DIM * D_DIM * P_DIM * T_DIM * F_DIM;

    dedisp_prep_kernel<<<1, 512>>>(dm, df);

    const int nblocks = B_DIM * D_DIM * P_DIM * (T_DIM / T_PER_BLOCK); // 16384

    cudaLaunchConfig_t cfg = {};
    cfg.gridDim  = dim3(nblocks, 1, 1);
    cfg.blockDim = dim3(256, 1, 1);
    cfg.dynamicSmemBytes = 0;
    cfg.stream = 0;

    cudaLaunchAttribute attrs[1];
    attrs[0].id = cudaLaunchAttributeProgrammaticStreamSerialization;
    attrs[0].val.programmaticStreamSerializationAllowed = 1;
    cfg.attrs = attrs;
    cfg.numAttrs = 1;

    cudaLaunchKernelEx(&cfg, dedisp_gather_kernel,
                       (const float4*)x, (float4*)out, dm, df, delays);
}

// round 11
// speedup vs baseline: 1.0003x; 1.0003x over previous
#include <cuda_runtime.h>
#include <cstdint>

// Problem constants (fixed shapes per reference)
#define B_DIM 4
#define P_DIM 2
#define T_DIM 1024
#define F_DIM 1024
#define D_DIM 16
#define CHUNK 128
#define NCHUNK (F_DIM / CHUNK)   // 8
#define T_PER_BLOCK 8

// Per-(b,d,chunk) integer shifts. 4*16*8 = 512 ints.
__device__ int g_shift[B_DIM * D_DIM * NCHUNK];

// ---------------------------------------------------------------------------
// Kernel 1 (tiny): compute the 512 chunk shifts. One block, 512 threads,
// thread (bd, c) does the sequential rounded-product sum that exactly
// reproduces the reference's trunc(chunk_mean) (rel_err == 0.0 verified).
// Publishes g_shift, then triggers PDL dependents.
// ---------------------------------------------------------------------------
__global__ void dedisp_prep_kernel(const float* __restrict__ dm,
                                   const float* __restrict__ df)
{
    const int idx = threadIdx.x;          // 0..511
    const int bd  = idx >> 3;             // (b*16 + d)
    const int c   = idx & (NCHUNK - 1);   // chunk

    const float dmv = dm[bd];
    const float* base = df + c * CHUNK;

    float sum = 0.0f;
    #pragma unroll 16
    for (int i = 0; i < CHUNK; i++)
        sum = __fadd_rn(sum, __fmul_rn(dmv, base[i]));  // round mul, then add

    const float mean = __fmul_rn(sum, 0.0078125f);       // exact *2^-7
    int s = (int)truncf(mean);
    if (s < 0) s = 0;
    g_shift[idx] = s & (T_DIM - 1);

    __threadfence();
    // Allow the PDL-dependent gather grid to launch now.
    asm volatile("griddepcontrol.launch_dependents;" ::: "memory");
}

// ---------------------------------------------------------------------------
// Kernel 2: the gather-copy (identical memory behavior to the 83.2us R7
// kernel: float4 loads via __ldg, normal float4 stores).
// grid = B*D*P*(T/T_PER_BLOCK) = 16384 blocks, 256 threads.
// Warp w handles chunk w -> shift is warp-uniform.
// The delays tail is written by the 64 (p==0, tb==0) blocks BEFORE the
// grid-dependency wait, so it overlaps the prep kernel.
// ---------------------------------------------------------------------------
__global__ __launch_bounds__(256)
void dedisp_gather_kernel(const float4* __restrict__ x,
                          float4*       __restrict__ out,
                          const float*  __restrict__ dm,
                          const float*  __restrict__ df,
                          float*        __restrict__ delays)
{
    const int bi = blockIdx.x;
    const int tb = bi & (T_DIM / T_PER_BLOCK - 1);   // 0..127
    const int p  = (bi >> 7) & (P_DIM - 1);
    const int d  = (bi >> 8) & (D_DIM - 1);
    const int b  = bi >> 12;
    const int bd = b * D_DIM + d;

    const int tid = threadIdx.x;          // 0..255, f4 index
    const int c   = tid >> 5;             // chunk = warp id

    // Pre-wait work: delays tail (independent of shifts).
    if (p == 0 && tb == 0) {
        const float dmv = dm[bd];
        float* drow = delays + (size_t)bd * F_DIM;
        #pragma unroll
        for (int j = 0; j < 4; j++) {
            const int f = tid + j * 256;                 // coalesced
            drow[f] = __fmul_rn(dmv, df[f]);
        }
    }

    // Wait for the prep kernel's g_shift to be published (PDL).
    asm volatile("griddepcontrol.wait;" ::: "memory");

    const int s = g_shift[bd * NCHUNK + c];

    const int F4 = F_DIM / 4;             // 256 float4 per row

    const float4* __restrict__ xrow =
        x + (size_t)(b * P_DIM + p) * T_DIM * F4;

    float4* __restrict__ orow =
        out + ((size_t)(bd * P_DIM + p) * T_DIM
               + (size_t)tb * T_PER_BLOCK) * F4 + tid;

    const int t0 = tb * T_PER_BLOCK;

    #pragma unroll
    for (int k = 0; k < T_PER_BLOCK; k++) {
        int ts = t0 + k + s;
        if (ts >= T_DIM) ts -= T_DIM;     // s < 1024, t < 1024 -> one subtract
        orow[k * F4] = __ldg(&xrow[(size_t)ts * F4 + tid]);
    }
}

// ---------------------------------------------------------------------------
// Launch: prep, then gather as a PDL-dependent launch on the same stream.
// ---------------------------------------------------------------------------
extern "C" void kernel_launch(void* const* d_in, const int* in_sizes, int n_in,
                              void* d_out, int out_size)
{
    const float* x  = (const float*)d_in[0];   // (4,2,1024,1024)
    const float* dm = (const float*)d_in[1];   // (4,16)
    const float* df = (const float*)d_in[2];   // (1024,)

    float* out = (float*)d_out;
    // Output layout: dedispersed (4,16,2,1024,1024) then delays (4,16,1024)
    float* delays = out + (size_t)B_DIM * D_DIM * P_DIM * T_DIM * F_DIM;

    dedisp_prep_kernel<<<1, 512>>>(dm, df);

    const int nblocks = B_DIM * D_DIM * P_DIM * (T_DIM / T_PER_BLOCK); // 16384

    cudaLaunchConfig_t cfg = {};
    cfg.gridDim  = dim3(nblocks, 1, 1);
    cfg.blockDim = dim3(256, 1, 1);
    cfg.dynamicSmemBytes = 0;
    cfg.stream = 0;

    cudaLaunchAttribute attrs[1];
    attrs[0].id = cudaLaunchAttributeProgrammaticStreamSerialization;
    attrs[0].val.programmaticStreamSerializationAllowed = 1;
    cfg.attrs = attrs;
    cfg.numAttrs = 1;

    cudaLaunchKernelEx(&cfg, dedisp_gather_kernel,
                       (const float4*)x, (float4*)out, dm, df, delays);
}